// round 16
// baseline (speedup 1.0000x reference)
#include <cuda_runtime.h>

// Dynamic grouped conv, algebraically reduced:
//   out[b,o,h,w] = sum_{kh,kw} ker[b,o,kh,kw] * S[b,g,h+kh,w+kw]
//   S[b,g] = sum of the 8 input channels of group g (reflection-padded)
//
// R16: R15 pipeline at full-chip residency. 64x128 bands (2 tiles), grid=512,
// 4 CTAs/SM (single wave, 592 slots). Prefetch split into two 4-channel
// batches (la[4]+ps) and 1 output channel/thread to fit 62 regs.

static constexpr int HH = 256;
static constexpr int WW = 256;
static constexpr int IN_CH = 64;
static constexpr int OUT_CH = 64;
static constexpr int FPG = 8;
static constexpr int TW = 64;
static constexpr int SSTR = 72;               // smem row stride in floats
static constexpr int PLANE  = HH * WW;        // 65536
static constexpr int PLANE4 = PLANE / 4;      // 16384
// smem col layout: halo(-1) -> 3, interior c -> c+4 (16B aligned), halo(64) -> 68

__device__ __forceinline__ int refl(int i, int n) {
    i = (i < 0) ? -i : i;
    return (i >= n) ? (2 * n - 2 - i) : i;
}

__global__ __launch_bounds__(256, 4)
void dynconv_pipe(const float* __restrict__ x,
                  const float* __restrict__ rep,
                  const float* __restrict__ Wm,
                  float* __restrict__ out) {
    __shared__ float S[2][66 * SSTR];          // 2 x 19 KB ping-pong
    __shared__ float wk[FPG * 9];

    const int bz  = blockIdx.z;                // b*8 + g
    const int b   = bz >> 3;
    const int g   = bz & 7;
    const int tx0 = blockIdx.x * TW;
    const int by0 = blockIdx.y * 128;          // band top row
    const int tid = threadIdx.x;

    // ---- threads 0..71: this block's 72 dynamic weights ----
    if (tid < FPG * 9) {
        const int j = (g * FPG) * 9 + tid;     // row of W (576 x 32)
        const float* r = rep + b * 32;
        const float* w = Wm + j * 32;
        float acc = 0.f;
        #pragma unroll
        for (int i = 0; i < 32; i++) acc = fmaf(r[i], w[i], acc);
        wk[tid] = (acc > 0.f) ? acc : 0.1f * acc;
    }

    const float* xb = x + (size_t)(b * IN_CH + g * FPG) * PLANE;

    // ---- tile 0 full load into S[0] (proven R4 ragged-loop form) ----
    for (int pos = tid; pos < 1056; pos += 256) {
        const int r  = pos >> 4;
        const int c4 = pos & 15;
        const int gy = refl(by0 + r - 1, HH);
        const float4* p = (const float4*)(xb + (size_t)gy * WW + tx0) + c4;
        float4 a = p[0];
        #pragma unroll
        for (int f = 1; f < FPG; f++) {
            float4 v = p[f * PLANE4];
            a.x += v.x; a.y += v.y; a.z += v.z; a.w += v.w;
        }
        *(float4*)&S[0][r * SSTR + 4 + 4 * c4] = a;
    }
    if (tid < 132) {
        const int r    = tid >> 1;
        const int side = tid & 1;
        const int gy = refl(by0 + r - 1, HH);
        const int gx = side ? refl(tx0 + 64, WW) : refl(tx0 - 1, WW);
        const float* p = xb + (size_t)gy * WW + gx;
        float a = 0.f;
        #pragma unroll
        for (int f = 0; f < FPG; f++) a += p[f * PLANE];
        S[0][r * SSTR + (side ? 68 : 3)] = a;
    }
    __syncthreads();

    // ---- stencil mapping: tid = col4(4b) | ch(3b) | rowq(1b) ----
    const int col4 = tid & 15;                 // 16 float4 columns
    const int ch   = (tid >> 4) & 7;           // 1 output channel per thread
    const int rowq = tid >> 7;                 // 2 strips of 32 rows
    const int py0  = rowq * 32;
    const int c0   = 4 * col4;

    float wreg[9];
    #pragma unroll
    for (int k = 0; k < 9; k++) wreg[k] = wk[ch * 9 + k];

    #pragma unroll
    for (int t = 0; t < 2; t++) {
        float* Sc = S[t];
        float* Sn = S[t ^ 1];
        const int gy0 = by0 + t * 64;          // this tile's top output row
        const int pr0 = gy0 + 64 - 1;          // next tile's padded top row
        const bool PREF = (t == 0);

        // rolling 3-row tap window
        float v[3][6];
        #pragma unroll
        for (int kh = 0; kh < 2; kh++) {
            const float* row = &Sc[(py0 + kh) * SSTR + c0 + 3];
            v[kh][0] = row[0];
            float4 q = *(const float4*)(row + 1);
            v[kh][1] = q.x; v[kh][2] = q.y; v[kh][3] = q.z; v[kh][4] = q.w;
            v[kh][5] = row[5];
        }
        const float* srow = &Sc[(py0 + 2) * SSTR + c0 + 3];

        float* ob = out + ((size_t)(b * OUT_CH + g * FPG + ch) * HH
                           + gy0 + py0) * WW + tx0 + c0;

        float4 la[4];
        float4 ps;
        int ppos = 0;

        for (int jo = 0; jo < 4; jo++) {       // 4 chunks of 8 rows (runtime)
            #pragma unroll
            for (int ji = 0; ji < 8; ji++) {
                // --- prefetch schedule: one position chunk per 8 rows ---
                if (PREF && ji == 0) {
                    ppos = tid + jo * 256;
                    const int rr  = ppos >> 4;
                    const int cc4 = ppos & 15;
                    const int gy  = refl(pr0 + rr, HH);
                    const float4* p = (const float4*)(xb + (size_t)gy * WW + tx0) + cc4;
                    #pragma unroll
                    for (int f = 0; f < 4; f++) la[f] = p[f * PLANE4];
                }
                if (PREF && ji == 1) {
                    ps.x = (la[0].x + la[1].x) + (la[2].x + la[3].x);
                    ps.y = (la[0].y + la[1].y) + (la[2].y + la[3].y);
                    ps.z = (la[0].z + la[1].z) + (la[2].z + la[3].z);
                    ps.w = (la[0].w + la[1].w) + (la[2].w + la[3].w);
                    const int rr  = ppos >> 4;
                    const int cc4 = ppos & 15;
                    const int gy  = refl(pr0 + rr, HH);
                    const float4* p = (const float4*)(xb + (size_t)gy * WW + tx0) + cc4;
                    #pragma unroll
                    for (int f = 0; f < 4; f++) la[f] = p[(f + 4) * PLANE4];
                }
                if (PREF && ji == 3) {
                    ps.x += (la[0].x + la[1].x) + (la[2].x + la[3].x);
                    ps.y += (la[0].y + la[1].y) + (la[2].y + la[3].y);
                    ps.z += (la[0].z + la[1].z) + (la[2].z + la[3].z);
                    ps.w += (la[0].w + la[1].w) + (la[2].w + la[3].w);
                    const int rr  = ppos >> 4;
                    const int cc4 = ppos & 15;
                    *(float4*)&Sn[rr * SSTR + 4 + 4 * cc4] = ps;
                }

                // --- stencil row ---
                v[2][0] = srow[0];
                {
                    float4 q = *(const float4*)(srow + 1);
                    v[2][1] = q.x; v[2][2] = q.y; v[2][3] = q.z; v[2][4] = q.w;
                }
                v[2][5] = srow[5];
                srow += SSTR;

                float4 acc;
                float* ap = (float*)&acc;
                #pragma unroll
                for (int i = 0; i < 4; i++) {
                    float a = 0.f;
                    #pragma unroll
                    for (int kh = 0; kh < 3; kh++)
                        #pragma unroll
                        for (int kw = 0; kw < 3; kw++)
                            a = fmaf(wreg[kh * 3 + kw], v[kh][i + kw], a);
                    ap[i] = a;
                }
                *(float4*)ob = acc;
                ob += WW;

                #pragma unroll
                for (int q = 0; q < 6; q++) { v[0][q] = v[1][q]; v[1][q] = v[2][q]; }
            }
        }

        // next-tile tail (positions 1024..1055) + halo columns
        if (PREF) {
            if (tid < 32) {
                const int pos = 1024 + tid;
                const int r  = pos >> 4;
                const int c4 = pos & 15;
                const int gy = refl(pr0 + r, HH);
                const float4* p = (const float4*)(xb + (size_t)gy * WW + tx0) + c4;
                float4 a = p[0];
                #pragma unroll
                for (int f = 1; f < FPG; f++) {
                    float4 vv = p[f * PLANE4];
                    a.x += vv.x; a.y += vv.y; a.z += vv.z; a.w += vv.w;
                }
                *(float4*)&Sn[r * SSTR + 4 + 4 * c4] = a;
            }
            if (tid < 132) {
                const int r    = tid >> 1;
                const int side = tid & 1;
                const int gy = refl(pr0 + r, HH);
                const int gx = side ? refl(tx0 + 64, WW) : refl(tx0 - 1, WW);
                const float* p = xb + (size_t)gy * WW + gx;
                float a = 0.f;
                #pragma unroll
                for (int f = 0; f < FPG; f++) a += p[f * PLANE];
                Sn[r * SSTR + (side ? 68 : 3)] = a;
            }
        }
        __syncthreads();
    }
}

extern "C" void kernel_launch(void* const* d_in, const int* in_sizes, int n_in,
                              void* d_out, int out_size) {
    const float* x   = (const float*)d_in[0];
    const float* rep = (const float*)d_in[1];
    const float* Wm  = (const float*)d_in[2];
    float* out = (float*)d_out;

    dim3 grid(WW / TW, 2, 8 * 8);              // 4 cols x 2 band-halves x 64 = 512
    dynconv_pipe<<<grid, 256>>>(x, rep, Wm, out);
}